// round 13
// baseline (speedup 1.0000x reference)
#include <cuda_runtime.h>
#include <cstdint>

#define BB 32
#define NN 128
#define DD 64
#define HH 8

// intermediates (device globals — no allocation allowed)
__device__ float g_Q[BB*NN*DD];
__device__ float g_K[BB*NN*DD];
__device__ float g_V[BB*NN*DD];
__device__ float g_attn[BB*NN*DD];

// ---------------------------------------------------------------------------
// helpers (portable PTX ISA, sm_80+, compiles for plain sm_103)
// ---------------------------------------------------------------------------
__device__ __forceinline__ void mma_bf16(float* c, const uint32_t* a, const uint32_t* b){
    asm("mma.sync.aligned.m16n8k16.row.col.f32.bf16.bf16.f32 "
        "{%0,%1,%2,%3}, {%4,%5,%6,%7}, {%8,%9}, {%0,%1,%2,%3};"
        : "+f"(c[0]), "+f"(c[1]), "+f"(c[2]), "+f"(c[3])
        : "r"(a[0]), "r"(a[1]), "r"(a[2]), "r"(a[3]), "r"(b[0]), "r"(b[1]));
}
// hi = {top16(x) low half, top16(y) high half}; lo = bf16x2 of residuals
__device__ __forceinline__ void split_pair(float x, float y, uint32_t &hi, uint32_t &lo){
    asm("prmt.b32 %0, %1, %2, 0x7632;" : "=r"(hi)
        : "r"(__float_as_uint(x)), "r"(__float_as_uint(y)));
    const float rx = x - __uint_as_float(__float_as_uint(x) & 0xFFFF0000u);
    const float ry = y - __uint_as_float(__float_as_uint(y) & 0xFFFF0000u);
    asm("cvt.rn.bf16x2.f32 %0, %1, %2;" : "=r"(lo) : "f"(ry), "f"(rx)); // low=rx, high=ry
}
__device__ __forceinline__ uint32_t smem_u32(const void* p){
    uint32_t a;
    asm("{ .reg .u64 t; cvta.to.shared.u64 t, %1; cvt.u32.u64 %0, t; }" : "=r"(a) : "l"(p));
    return a;
}
#define CP_ASYNC16(dst, src) \
    asm volatile("cp.async.ca.shared.global [%0], [%1], 16;" :: "r"(dst), "l"(src))
#define CP_COMMIT() asm volatile("cp.async.commit_group;" ::: "memory")
#define CP_WAIT0()  asm volatile("cp.async.wait_group 0;" ::: "memory")

// smem layout (float offsets).
// Region1 (9216 f): epair [128][72] -> V tile [128][68]
// Region2 (4608 f): Bpair [64][72]  -> scores [8][132] + reduction [1024]
#define EP_OFF 0
#define V_OFF  0
#define B_OFF  9216
#define SS_OFF 9216
#define RED_OFF 10272          // 9216 + 1056, reduction 1024 f, ends 11296
#define SQ_OFF 13824
#define SRW_OFF 13888
#define ATTN_F 14016
#define ATTN_SMEM_BYTES (ATTN_F*4)   // 56064 B -> 2 blocks/SM @ 512 thr

// ---------------------------------------------------------------------------
// Kernel 1: Q/K/V projections (proven)
// ---------------------------------------------------------------------------
__global__ __launch_bounds__(256) void qkv_kernel(
    const float* __restrict__ h,
    const float* __restrict__ Wq, const float* __restrict__ Wk, const float* __restrict__ Wv)
{
    extern __shared__ float sm_q[];
    float* sW = sm_q;
    float* sh = sm_q + 12288;
    const int t = threadIdx.x, c = t & 63, r = t >> 6;
    const int row0 = blockIdx.x * 8;
#pragma unroll
    for (int rep = 0; rep < 16; ++rep) sW[rep*256 + t]        = Wq[rep*256 + t];
#pragma unroll
    for (int rep = 0; rep < 16; ++rep) sW[4096 + rep*256 + t] = Wk[rep*256 + t];
#pragma unroll
    for (int rep = 0; rep < 16; ++rep) sW[8192 + rep*256 + t] = Wv[rep*256 + t];
    sh[t]       = h[row0*64 + t];
    sh[256 + t] = h[row0*64 + 256 + t];
    __syncthreads();

    const int rA = r, rB = r + 4;
    float q0=0,k0=0,v0=0,q1=0,k1=0,v1=0;
#pragma unroll 16
    for (int d = 0; d < 64; ++d){
        const float wq = sW[d*64 + c];
        const float wk = sW[4096 + d*64 + c];
        const float wv = sW[8192 + d*64 + c];
        const float xa = sh[rA*64 + d];
        const float xb = sh[rB*64 + d];
        q0 += xa*wq; k0 += xa*wk; v0 += xa*wv;
        q1 += xb*wq; k1 += xb*wk; v1 += xb*wv;
    }
    const float kscale = 0.35355339059327373f; // DH^-0.5
    g_Q[(row0+rA)*64 + c] = q0;
    g_K[(row0+rA)*64 + c] = k0 * kscale;
    g_V[(row0+rA)*64 + c] = v0;
    g_Q[(row0+rB)*64 + c] = q1;
    g_K[(row0+rB)*64 + c] = k1 * kscale;
    g_V[(row0+rB)*64 + c] = v1;
}

// ---------------------------------------------------------------------------
// Kernel 2: attention. One block per (i,b), 512 threads = 16 warps, 2 blk/SM.
// Warp w owns (m-tile mt = w>>1, n-half ng = (w&1)*4): acc is 16 regs.
// Numerics identical to R11: 3-limb bf16 GEMM, K via __ldg, V via cp.async.
// ---------------------------------------------------------------------------
__global__ __launch_bounds__(512, 2) void attn_kernel(
    const float* __restrict__ e,
    const float* __restrict__ We,
    const float* __restrict__ kRW)
{
    extern __shared__ __align__(16) float S[];
    const int t = threadIdx.x;
    const int w = t >> 5, l = t & 31;
    const int qq = l >> 2, rr = l & 3;      // fragment row / col-in-quad
    const int mt = w >> 1;                  // m-tile 0..7
    const int ng = (w & 1) * 4;             // n-tile group base
    const int i = blockIdx.x, b = blockIdx.y;
    const int bi = b*NN + i;

    if (t < 64) S[SQ_OFF + t] = g_Q[bi*64 + t];
    if (t < 128) S[SRW_OFF + t] = kRW[bi*128 + t];
    __syncthreads();

    // ---- stage e limbs: epair[j][kp][{hi,lo}], stride 72 (4 iters/thread) ----
    const float* eg = e + (size_t)bi * (NN*DD);
#pragma unroll
    for (int it = 0; it < 4; ++it){
        const int f = it*512 + t;
        const int j = f >> 4, q4 = f & 15;
        const float4 v = *reinterpret_cast<const float4*>(eg + j*64 + q4*4);
        uint32_t hiA, loA, hiB, loB;
        split_pair(v.x, v.y, hiA, loA);
        split_pair(v.z, v.w, hiB, loB);
        *reinterpret_cast<uint4*>(&S[EP_OFF + j*72 + q4*4]) = make_uint4(hiA, loA, hiB, loB);
    }
    // ---- stage B limbs: Bpair[hk][dp][{hi,lo}], stride 72 ----
    // FULL coverage: 4 reps x 512 threads = 2048 items = 64 hk x 32 d-pairs.
#pragma unroll
    for (int rep = 0; rep < 4; ++rep){
        const int idx = rep*512 + t;
        const int hk = idx & 63, dp = idx >> 6;   // dp in [0,32)
        const float sq = S[SQ_OFF + hk];
        const float w0 = We[(2*dp)*64 + hk] * sq;
        const float w1 = We[(2*dp+1)*64 + hk] * sq;
        uint32_t hi, lo;
        split_pair(w0, w1, hi, lo);
        *reinterpret_cast<uint2*>(&S[B_OFF + hk*72 + dp*2]) = make_uint2(hi, lo);
    }
    __syncthreads();

    // ---- GEMM: warp owns m-tile mt, n-tiles [ng, ng+4); 4 ks ----
    float acc[4][4];
#pragma unroll
    for (int n = 0; n < 4; ++n)
#pragma unroll
        for (int x = 0; x < 4; ++x) acc[n][x] = 0.f;

#pragma unroll
    for (int ks = 0; ks < 4; ++ks){
        // A fragments for this warp's m-tile (8 regs live)
        uint32_t Ah[4], Al[4];
        {
            const int row = 16*mt + qq;
            const int base = EP_OFF + row*72 + (ks*8 + rr)*2;
            const uint2 a0 = *reinterpret_cast<const uint2*>(&S[base]);
            const uint2 a1 = *reinterpret_cast<const uint2*>(&S[base + 8*72]);
            const uint2 a2 = *reinterpret_cast<const uint2*>(&S[base + 8]);
            const uint2 a3 = *reinterpret_cast<const uint2*>(&S[base + 8*72 + 8]);
            Ah[0] = a0.x; Al[0] = a0.y;
            Ah[1] = a1.x; Al[1] = a1.y;
            Ah[2] = a2.x; Al[2] = a2.y;
            Ah[3] = a3.x; Al[3] = a3.y;
        }
        // stream B per n-tile: only 4 B regs live at a time
#pragma unroll
        for (int n = 0; n < 4; ++n){
            const int nt = ng + n;
            const int bbase = B_OFF + (nt*8 + qq)*72 + (ks*8 + rr)*2;
            const uint2 b0 = *reinterpret_cast<const uint2*>(&S[bbase]);
            const uint2 b1 = *reinterpret_cast<const uint2*>(&S[bbase + 8]);
            uint32_t Bh[2] = {b0.x, b1.x};
            uint32_t Bl[2] = {b0.y, b1.y};
            mma_bf16(acc[n], Ah, Bh);
            mma_bf16(acc[n], Al, Bh);
            mma_bf16(acc[n], Ah, Bl);
        }
    }
    __syncthreads();   // all frag reads done; both regions free

    // ---- prefetch V into the freed e-region via cp.async (overlaps score) ----
    {
        const uint32_t sbase = smem_u32(S);
        const float* Vg = g_V + (size_t)b*NN*64;
#pragma unroll
        for (int it = 0; it < 4; ++it){
            const int f = it*512 + t;
            const int j = f >> 4, q4 = f & 15;
            CP_ASYNC16(sbase + (uint32_t)(V_OFF + j*68 + q4*4)*4u, Vg + j*64 + q4*4);
        }
        CP_COMMIT();
    }

    // ---- score phase: acc regs + K direct from L2, quad butterfly reduce ----
    const float* Kg = g_K + (size_t)b*NN*64;
#pragma unroll
    for (int rh = 0; rh < 2; ++rh){
        const int row = 16*mt + qq + 8*rh;
        const float* Kr = Kg + row*64 + 2*rr;
        float sc4[4];
#pragma unroll
        for (int n = 0; n < 4; ++n){
            const int nt = ng + n;
            const float2 k2 = __ldg(reinterpret_cast<const float2*>(Kr + 8*nt));
            float p = acc[n][2*rh]*k2.x + acc[n][2*rh+1]*k2.y;
            p += __shfl_xor_sync(0xffffffffu, p, 1);
            p += __shfl_xor_sync(0xffffffffu, p, 2);
            sc4[n] = p;
        }
        // thread rr writes n-tile ng+rr (each quad thread owns one)
        const float rw = S[SRW_OFF + row];
        const float s = fminf(fmaxf(sc4[rr], -5.f), 5.f);
        S[SS_OFF + (ng + rr)*132 + row] = __expf(s) * rw;
    }
    CP_WAIT0();
    __syncthreads();

    // ---- attn = (sS @ V) / denom, V from smem; 8-way j-split over u ----
    {
        const int o = t & 63, u = t >> 6;       // u in [0,8)
        const int hR = o >> 3;
        const float* Sr = S + SS_OFF + hR*132 + u*16;
        float vsum = 0.f, dsum = 0.f;
#pragma unroll
        for (int jj = 0; jj < 16; ++jj){
            const float s = Sr[jj];
            vsum += s * S[V_OFF + (u*16 + jj)*68 + o];
            dsum += s;
        }
        S[RED_OFF + t]       = vsum;
        S[RED_OFF + 512 + t] = dsum;
    }
    __syncthreads();
    if (t < 64){
        float v = 0.f, d = 0.f;
#pragma unroll
        for (int u = 0; u < 8; ++u){
            v += S[RED_OFF + u*64 + t];
            d += S[RED_OFF + 512 + u*64 + t];
        }
        g_attn[bi*64 + t] = v / fmaxf(d, 1e-6f);
    }
}

// ---------------------------------------------------------------------------
// Kernel 3: O-proj + residual + LN1 + FFN + LN2 (proven)
// ---------------------------------------------------------------------------
__global__ __launch_bounds__(256) void tail_kernel(
    const float* __restrict__ h,
    const float* __restrict__ Wo, const float* __restrict__ bo,
    const float* __restrict__ g1, const float* __restrict__ b1g,
    const float* __restrict__ W1, const float* __restrict__ b1,
    const float* __restrict__ W2, const float* __restrict__ b2,
    const float* __restrict__ g2, const float* __restrict__ b2g,
    float* __restrict__ out)
{
    __shared__ float sa[4][65];
    __shared__ float sx[4][65];
    __shared__ float shd[4][130];
    const int t = threadIdx.x, r = t >> 6, c = t & 63;
    const int row = blockIdx.x * 4 + r;

    sa[r][c] = g_attn[row*64 + c];
    __syncthreads();
    float x = bo[c] + h[row*64 + c];
#pragma unroll 8
    for (int d = 0; d < 64; ++d) x += sa[r][d] * Wo[d*64 + c];

    sx[r][c] = x;
    __syncthreads();
    float m = 0.f;
#pragma unroll 8
    for (int d = 0; d < 64; ++d) m += sx[r][d];
    m *= (1.f/64.f);
    float v = 0.f;
#pragma unroll 8
    for (int d = 0; d < 64; ++d){ const float df = sx[r][d] - m; v += df*df; }
    v *= (1.f/64.f);
    const float h1 = (x - m) * rsqrtf(v + 1e-5f) * g1[c] + b1g[c];
    __syncthreads();
    sx[r][c] = h1;
    __syncthreads();

    float a0 = b1[c], a1 = b1[c + 64];
#pragma unroll 8
    for (int d = 0; d < 64; ++d){
        const float xv = sx[r][d];
        a0 += xv * W1[d*128 + c];
        a1 += xv * W1[d*128 + c + 64];
    }
    shd[r][c]      = fmaxf(a0, 0.f);
    shd[r][c + 64] = fmaxf(a1, 0.f);
    __syncthreads();
    float ff = b2[c];
#pragma unroll 8
    for (int u = 0; u < 128; ++u) ff += shd[r][u] * W2[u*64 + c];
    const float x2 = h1 + ff;

    __syncthreads();
    sa[r][c] = x2;
    __syncthreads();
    float m2 = 0.f;
#pragma unroll 8
    for (int d = 0; d < 64; ++d) m2 += sa[r][d];
    m2 *= (1.f/64.f);
    float v2 = 0.f;
#pragma unroll 8
    for (int d = 0; d < 64; ++d){ const float df = sa[r][d] - m2; v2 += df*df; }
    v2 *= (1.f/64.f);
    out[row*64 + c] = (x2 - m2) * rsqrtf(v2 + 1e-5f) * g2[c] + b2g[c];
}

// ---------------------------------------------------------------------------
extern "C" void kernel_launch(void* const* d_in, const int* in_sizes, int n_in,
                              void* d_out, int out_size)
{
    (void)in_sizes; (void)n_in; (void)out_size;
    const float* h   = (const float*)d_in[0];
    const float* e   = (const float*)d_in[2];
    const float* kRW = (const float*)d_in[3];
    const float* Wq  = (const float*)d_in[4];
    const float* Wk  = (const float*)d_in[5];
    const float* We  = (const float*)d_in[6];
    const float* Wv  = (const float*)d_in[7];
    const float* Wo  = (const float*)d_in[8];
    const float* bo  = (const float*)d_in[9];
    const float* g1  = (const float*)d_in[10];
    const float* b1g = (const float*)d_in[11];
    const float* W1  = (const float*)d_in[12];
    const float* b1  = (const float*)d_in[13];
    const float* W2  = (const float*)d_in[14];
    const float* b2  = (const float*)d_in[15];
    const float* g2  = (const float*)d_in[16];
    const float* b2g = (const float*)d_in[17];
    float* out = (float*)d_out;

    const int qkv_smem = 12800 * 4;
    cudaFuncSetAttribute((const void*)qkv_kernel,
                         cudaFuncAttributeMaxDynamicSharedMemorySize, qkv_smem);
    cudaFuncSetAttribute((const void*)attn_kernel,
                         cudaFuncAttributeMaxDynamicSharedMemorySize, ATTN_SMEM_BYTES);

    qkv_kernel<<<BB*NN/8, 256, qkv_smem>>>(h, Wq, Wk, Wv);
    dim3 grid(NN, BB);
    attn_kernel<<<grid, 512, ATTN_SMEM_BYTES>>>(e, We, kRW);
    tail_kernel<<<BB*NN/4, 256>>>(h, Wo, bo, g1, b1g, W1, b1, W2, b2, g2, b2g, out);
}

// round 14
// speedup vs baseline: 1.0493x; 1.0493x over previous
#include <cuda_runtime.h>
#include <cstdint>

#define BB 32
#define NN 128
#define DD 64
#define HH 8

// intermediates (device globals — no allocation allowed)
__device__ float g_Q[BB*NN*DD];
__device__ float g_K[BB*NN*DD];
__device__ float g_V[BB*NN*DD];
__device__ float g_attn[BB*NN*DD];

// ---------------------------------------------------------------------------
// helpers (portable PTX ISA, sm_80+, compiles for plain sm_103)
// ---------------------------------------------------------------------------
__device__ __forceinline__ void mma_bf16(float* c, const uint32_t* a, const uint32_t* b){
    asm("mma.sync.aligned.m16n8k16.row.col.f32.bf16.bf16.f32 "
        "{%0,%1,%2,%3}, {%4,%5,%6,%7}, {%8,%9}, {%0,%1,%2,%3};"
        : "+f"(c[0]), "+f"(c[1]), "+f"(c[2]), "+f"(c[3])
        : "r"(a[0]), "r"(a[1]), "r"(a[2]), "r"(a[3]), "r"(b[0]), "r"(b[1]));
}
// hi = {top16(x) low half, top16(y) high half}; lo = bf16x2 of residuals
__device__ __forceinline__ void split_pair(float x, float y, uint32_t &hi, uint32_t &lo){
    asm("prmt.b32 %0, %1, %2, 0x7632;" : "=r"(hi)
        : "r"(__float_as_uint(x)), "r"(__float_as_uint(y)));
    const float rx = x - __uint_as_float(__float_as_uint(x) & 0xFFFF0000u);
    const float ry = y - __uint_as_float(__float_as_uint(y) & 0xFFFF0000u);
    asm("cvt.rn.bf16x2.f32 %0, %1, %2;" : "=r"(lo) : "f"(ry), "f"(rx)); // low=rx, high=ry
}
__device__ __forceinline__ uint32_t smem_u32(const void* p){
    uint32_t a;
    asm("{ .reg .u64 t; cvta.to.shared.u64 t, %1; cvt.u32.u64 %0, t; }" : "=r"(a) : "l"(p));
    return a;
}
#define CP_ASYNC16(dst, src) \
    asm volatile("cp.async.ca.shared.global [%0], [%1], 16;" :: "r"(dst), "l"(src))
#define CP_COMMIT() asm volatile("cp.async.commit_group;" ::: "memory")
#define CP_WAIT0()  asm volatile("cp.async.wait_group 0;" ::: "memory")

// smem layout (float offsets).
// Region1 (9216 f): epair [128][72] -> V tile [128][68] + reduction [512] @8704
// Region2 (4608 f): Bpair [64][72]  -> scores [8][132]
#define EP_OFF 0
#define V_OFF  0
#define RED_OFF 8704
#define B_OFF  9216
#define SS_OFF 9216
#define SQ_OFF 13824
#define SRW_OFF 13888
#define ATTN_F 14016
#define ATTN_SMEM_BYTES (ATTN_F*4)   // 56064 B -> 4 blocks/SM (224256 <= 228KB)

// ---------------------------------------------------------------------------
// Kernel 1: Q/K/V projections (proven)
// ---------------------------------------------------------------------------
__global__ __launch_bounds__(256) void qkv_kernel(
    const float* __restrict__ h,
    const float* __restrict__ Wq, const float* __restrict__ Wk, const float* __restrict__ Wv)
{
    extern __shared__ float sm_q[];
    float* sW = sm_q;
    float* sh = sm_q + 12288;
    const int t = threadIdx.x, c = t & 63, r = t >> 6;
    const int row0 = blockIdx.x * 8;
#pragma unroll
    for (int rep = 0; rep < 16; ++rep) sW[rep*256 + t]        = Wq[rep*256 + t];
#pragma unroll
    for (int rep = 0; rep < 16; ++rep) sW[4096 + rep*256 + t] = Wk[rep*256 + t];
#pragma unroll
    for (int rep = 0; rep < 16; ++rep) sW[8192 + rep*256 + t] = Wv[rep*256 + t];
    sh[t]       = h[row0*64 + t];
    sh[256 + t] = h[row0*64 + 256 + t];
    __syncthreads();

    const int rA = r, rB = r + 4;
    float q0=0,k0=0,v0=0,q1=0,k1=0,v1=0;
#pragma unroll 16
    for (int d = 0; d < 64; ++d){
        const float wq = sW[d*64 + c];
        const float wk = sW[4096 + d*64 + c];
        const float wv = sW[8192 + d*64 + c];
        const float xa = sh[rA*64 + d];
        const float xb = sh[rB*64 + d];
        q0 += xa*wq; k0 += xa*wk; v0 += xa*wv;
        q1 += xb*wq; k1 += xb*wk; v1 += xb*wv;
    }
    const float kscale = 0.35355339059327373f; // DH^-0.5
    g_Q[(row0+rA)*64 + c] = q0;
    g_K[(row0+rA)*64 + c] = k0 * kscale;
    g_V[(row0+rA)*64 + c] = v0;
    g_Q[(row0+rB)*64 + c] = q1;
    g_K[(row0+rB)*64 + c] = k1 * kscale;
    g_V[(row0+rB)*64 + c] = v1;
}

// ---------------------------------------------------------------------------
// Kernel 2: attention. One block per (i,b), 256 threads = 8 warps, 4 blk/SM.
// Warp w owns m-tile w. B fragments streamed per n-tile (~55 live regs,
// fits the 64-reg budget of __launch_bounds__(256,4) without spills).
// Numerics identical to R11: 3-limb bf16 GEMM, K via __ldg, V via cp.async.
// ---------------------------------------------------------------------------
__global__ __launch_bounds__(256, 4) void attn_kernel(
    const float* __restrict__ e,
    const float* __restrict__ We,
    const float* __restrict__ kRW)
{
    extern __shared__ __align__(16) float S[];
    const int t = threadIdx.x;
    const int w = t >> 5, l = t & 31;
    const int qq = l >> 2, rr = l & 3;      // fragment row / col-in-quad
    const int i = blockIdx.x, b = blockIdx.y;
    const int bi = b*NN + i;

    if (t < 64) S[SQ_OFF + t] = g_Q[bi*64 + t];
    if (t < 128) S[SRW_OFF + t] = kRW[bi*128 + t];
    __syncthreads();

    // ---- stage e limbs: epair[j][kp][{hi,lo}], stride 72 (8 iters/thread) ----
    const float* eg = e + (size_t)bi * (NN*DD);
#pragma unroll
    for (int it = 0; it < 8; ++it){
        const int f = it*256 + t;
        const int j = f >> 4, q4 = f & 15;
        const float4 v = *reinterpret_cast<const float4*>(eg + j*64 + q4*4);
        uint32_t hiA, loA, hiB, loB;
        split_pair(v.x, v.y, hiA, loA);
        split_pair(v.z, v.w, hiB, loB);
        *reinterpret_cast<uint4*>(&S[EP_OFF + j*72 + q4*4]) = make_uint4(hiA, loA, hiB, loB);
    }
    // ---- stage B limbs: Bpair[hk][dp][{hi,lo}], stride 72 (8 iters/thread) ----
#pragma unroll
    for (int rep = 0; rep < 8; ++rep){
        const int idx = rep*256 + t;
        const int hk = idx & 63, dp = idx >> 6;
        const float sq = S[SQ_OFF + hk];
        const float w0 = We[(2*dp)*64 + hk] * sq;
        const float w1 = We[(2*dp+1)*64 + hk] * sq;
        uint32_t hi, lo;
        split_pair(w0, w1, hi, lo);
        *reinterpret_cast<uint2*>(&S[B_OFF + hk*72 + dp*2]) = make_uint2(hi, lo);
    }
    __syncthreads();

    // ---- GEMM: warp w owns m-tile w (rows 16w..16w+15); 8 n-tiles; 4 ks ----
    float acc[8][4];
#pragma unroll
    for (int n = 0; n < 8; ++n)
#pragma unroll
        for (int x = 0; x < 4; ++x) acc[n][x] = 0.f;

#pragma unroll
    for (int ks = 0; ks < 4; ++ks){
        // A fragments for this warp's m-tile (8 regs live)
        uint32_t Ah[4], Al[4];
        {
            const int row = 16*w + qq;
            const int base = EP_OFF + row*72 + (ks*8 + rr)*2;
            const uint2 a0 = *reinterpret_cast<const uint2*>(&S[base]);
            const uint2 a1 = *reinterpret_cast<const uint2*>(&S[base + 8*72]);
            const uint2 a2 = *reinterpret_cast<const uint2*>(&S[base + 8]);
            const uint2 a3 = *reinterpret_cast<const uint2*>(&S[base + 8*72 + 8]);
            Ah[0] = a0.x; Al[0] = a0.y;
            Ah[1] = a1.x; Al[1] = a1.y;
            Ah[2] = a2.x; Al[2] = a2.y;
            Ah[3] = a3.x; Al[3] = a3.y;
        }
        // stream B per n-tile: only 4 B regs live at a time
#pragma unroll
        for (int nt = 0; nt < 8; ++nt){
            const int bbase = B_OFF + (nt*8 + qq)*72 + (ks*8 + rr)*2;
            const uint2 b0 = *reinterpret_cast<const uint2*>(&S[bbase]);
            const uint2 b1 = *reinterpret_cast<const uint2*>(&S[bbase + 8]);
            uint32_t Bh[2] = {b0.x, b1.x};
            uint32_t Bl[2] = {b0.y, b1.y};
            mma_bf16(acc[nt], Ah, Bh);
            mma_bf16(acc[nt], Al, Bh);
            mma_bf16(acc[nt], Ah, Bl);
        }
    }
    __syncthreads();   // all frag reads done; both regions free

    // ---- prefetch V into the freed e-region via cp.async (overlaps score) ----
    {
        const uint32_t sbase = smem_u32(S);
        const float* Vg = g_V + (size_t)b*NN*64;
#pragma unroll
        for (int it = 0; it < 8; ++it){
            const int f = it*256 + t;
            const int j = f >> 4, q4 = f & 15;
            CP_ASYNC16(sbase + (uint32_t)(V_OFF + j*68 + q4*4)*4u, Vg + j*64 + q4*4);
        }
        CP_COMMIT();
    }

    // ---- score phase: acc regs + K direct from L2, quad butterfly reduce ----
    const float* Kg = g_K + (size_t)b*NN*64;
#pragma unroll
    for (int rh = 0; rh < 2; ++rh){
        const int row = 16*w + qq + 8*rh;
        const float* Kr = Kg + row*64 + 2*rr;
        float sc8[8];
#pragma unroll
        for (int nt = 0; nt < 8; ++nt){
            const float2 k2 = __ldg(reinterpret_cast<const float2*>(Kr + 8*nt));
            float p = acc[nt][2*rh]*k2.x + acc[nt][2*rh+1]*k2.y;
            p += __shfl_xor_sync(0xffffffffu, p, 1);
            p += __shfl_xor_sync(0xffffffffu, p, 2);
            sc8[nt] = p;
        }
        const float rw = S[SRW_OFF + row];
#pragma unroll
        for (int x = 0; x < 2; ++x){
            const int nt = 2*rr + x;
            const float s = fminf(fmaxf(sc8[nt], -5.f), 5.f);
            S[SS_OFF + nt*132 + row] = __expf(s) * rw;
        }
    }
    CP_WAIT0();
    __syncthreads();

    // ---- attn = (sS @ V) / denom, V from smem; 4-way j-split over u ----
    {
        const int o = t & 63, u = t >> 6;       // u in [0,4)
        const int hR = o >> 3;
        const float* Sr = S + SS_OFF + hR*132 + u*32;
        float vsum = 0.f, dsum = 0.f;
#pragma unroll
        for (int jj = 0; jj < 32; ++jj){
            const float s = Sr[jj];
            vsum += s * S[V_OFF + (u*32 + jj)*68 + o];
            dsum += s;
        }
        S[RED_OFF + t]       = vsum;
        S[RED_OFF + 256 + t] = dsum;
    }
    __syncthreads();
    if (t < 64){
        float v = 0.f, d = 0.f;
#pragma unroll
        for (int u = 0; u < 4; ++u){
            v += S[RED_OFF + u*64 + t];
            d += S[RED_OFF + 256 + u*64 + t];
        }
        g_attn[bi*64 + t] = v / fmaxf(d, 1e-6f);
    }
}

// ---------------------------------------------------------------------------
// Kernel 3: O-proj + residual + LN1 + FFN + LN2 (proven)
// ---------------------------------------------------------------------------
__global__ __launch_bounds__(256) void tail_kernel(
    const float* __restrict__ h,
    const float* __restrict__ Wo, const float* __restrict__ bo,
    const float* __restrict__ g1, const float* __restrict__ b1g,
    const float* __restrict__ W1, const float* __restrict__ b1,
    const float* __restrict__ W2, const float* __restrict__ b2,
    const float* __restrict__ g2, const float* __restrict__ b2g,
    float* __restrict__ out)
{
    __shared__ float sa[4][65];
    __shared__ float sx[4][65];
    __shared__ float shd[4][130];
    const int t = threadIdx.x, r = t >> 6, c = t & 63;
    const int row = blockIdx.x * 4 + r;

    sa[r][c] = g_attn[row*64 + c];
    __syncthreads();
    float x = bo[c] + h[row*64 + c];
#pragma unroll 8
    for (int d = 0; d < 64; ++d) x += sa[r][d] * Wo[d*64 + c];

    sx[r][c] = x;
    __syncthreads();
    float m = 0.f;
#pragma unroll 8
    for (int d = 0; d < 64; ++d) m += sx[r][d];
    m *= (1.f/64.f);
    float v = 0.f;
#pragma unroll 8
    for (int d = 0; d < 64; ++d){ const float df = sx[r][d] - m; v += df*df; }
    v *= (1.f/64.f);
    const float h1 = (x - m) * rsqrtf(v + 1e-5f) * g1[c] + b1g[c];
    __syncthreads();
    sx[r][c] = h1;
    __syncthreads();

    float a0 = b1[c], a1 = b1[c + 64];
#pragma unroll 8
    for (int d = 0; d < 64; ++d){
        const float xv = sx[r][d];
        a0 += xv * W1[d*128 + c];
        a1 += xv * W1[d*128 + c + 64];
    }
    shd[r][c]      = fmaxf(a0, 0.f);
    shd[r][c + 64] = fmaxf(a1, 0.f);
    __syncthreads();
    float ff = b2[c];
#pragma unroll 8
    for (int u = 0; u < 128; ++u) ff += shd[r][u] * W2[u*64 + c];
    const float x2 = h1 + ff;

    __syncthreads();
    sa[r][c] = x2;
    __syncthreads();
    float m2 = 0.f;
#pragma unroll 8
    for (int d = 0; d < 64; ++d) m2 += sa[r][d];
    m2 *= (1.f/64.f);
    float v2 = 0.f;
#pragma unroll 8
    for (int d = 0; d < 64; ++d){ const float df = sa[r][d] - m2; v2 += df*df; }
    v2 *= (1.f/64.f);
    out[row*64 + c] = (x2 - m2) * rsqrtf(v2 + 1e-5f) * g2[c] + b2g[c];
}

// ---------------------------------------------------------------------------
extern "C" void kernel_launch(void* const* d_in, const int* in_sizes, int n_in,
                              void* d_out, int out_size)
{
    (void)in_sizes; (void)n_in; (void)out_size;
    const float* h   = (const float*)d_in[0];
    const float* e   = (const float*)d_in[2];
    const float* kRW = (const float*)d_in[3];
    const float* Wq  = (const float*)d_in[4];
    const float* Wk  = (const float*)d_in[5];
    const float* We  = (const float*)d_in[6];
    const float* Wv  = (const float*)d_in[7];
    const float* Wo  = (const float*)d_in[8];
    const float* bo  = (const float*)d_in[9];
    const float* g1  = (const float*)d_in[10];
    const float* b1g = (const float*)d_in[11];
    const float* W1  = (const float*)d_in[12];
    const float* b1  = (const float*)d_in[13];
    const float* W2  = (const float*)d_in[14];
    const float* b2  = (const float*)d_in[15];
    const float* g2  = (const float*)d_in[16];
    const float* b2g = (const float*)d_in[17];
    float* out = (float*)d_out;

    const int qkv_smem = 12800 * 4;
    cudaFuncSetAttribute((const void*)qkv_kernel,
                         cudaFuncAttributeMaxDynamicSharedMemorySize, qkv_smem);
    cudaFuncSetAttribute((const void*)attn_kernel,
                         cudaFuncAttributeMaxDynamicSharedMemorySize, ATTN_SMEM_BYTES);

    qkv_kernel<<<BB*NN/8, 256, qkv_smem>>>(h, Wq, Wk, Wv);
    dim3 grid(NN, BB);
    attn_kernel<<<grid, 256, ATTN_SMEM_BYTES>>>(e, We, kRW);
    tail_kernel<<<BB*NN/4, 256>>>(h, Wo, bo, g1, b1g, W1, b1, W2, b2, g2, b2g, out);
}

// round 15
// speedup vs baseline: 1.1606x; 1.1061x over previous
#include <cuda_runtime.h>
#include <cuda_fp16.h>
#include <cstdint>

#define BB 32
#define NN 128
#define DD 64
#define HH 8

// intermediates (device globals — no allocation allowed)
__device__ float g_Q[BB*NN*DD];
__device__ float g_K[BB*NN*DD];
__device__ float g_V[BB*NN*DD];
__device__ float g_attn[BB*NN*DD];

// ---------------------------------------------------------------------------
// helpers (portable PTX ISA, sm_80+, compiles for plain sm_103)
// ---------------------------------------------------------------------------
__device__ __forceinline__ void mma_f16(float* c, const uint32_t* a, const uint32_t* b){
    asm("mma.sync.aligned.m16n8k16.row.col.f32.f16.f16.f32 "
        "{%0,%1,%2,%3}, {%4,%5,%6,%7}, {%8,%9}, {%0,%1,%2,%3};"
        : "+f"(c[0]), "+f"(c[1]), "+f"(c[2]), "+f"(c[3])
        : "r"(a[0]), "r"(a[1]), "r"(a[2]), "r"(a[3]), "r"(b[0]), "r"(b[1]));
}
// fp16 2-limb split of a float pair: hi = rn(x,y) packed; lo = rn(residuals)
__device__ __forceinline__ void split_pair_f16(float x, float y, uint32_t &hi, uint32_t &lo){
    const __half2 hh = __float22half2_rn(make_float2(x, y));
    const float2 bk = __half22float2(hh);
    const __half2 ll = __float22half2_rn(make_float2(x - bk.x, y - bk.y));
    hi = *reinterpret_cast<const uint32_t*>(&hh);
    lo = *reinterpret_cast<const uint32_t*>(&ll);
}
__device__ __forceinline__ uint32_t f16pack(float x, float y){
    const __half2 hh = __float22half2_rn(make_float2(x, y));
    return *reinterpret_cast<const uint32_t*>(&hh);
}
__device__ __forceinline__ uint32_t smem_u32(const void* p){
    uint32_t a;
    asm("{ .reg .u64 t; cvta.to.shared.u64 t, %1; cvt.u32.u64 %0, t; }" : "=r"(a) : "l"(p));
    return a;
}
#define CP_ASYNC16(dst, src) \
    asm volatile("cp.async.ca.shared.global [%0], [%1], 16;" :: "r"(dst), "l"(src))
#define CP_COMMIT() asm volatile("cp.async.commit_group;" ::: "memory")
#define CP_WAIT0()  asm volatile("cp.async.wait_group 0;" ::: "memory")

// smem layout (float offsets).
// Region1 (9216 f): epair [128][72] -> V tile [128][68] + reduction [512] @8704
// Region2 (2560 f): B fp16 [64][40] -> scores [8][132]
#define EP_OFF 0
#define V_OFF  0
#define RED_OFF 8704
#define B_OFF  9216
#define SS_OFF 9216
#define SQ_OFF 11776
#define SRW_OFF 11840
#define ATTN_F 11968
#define ATTN_SMEM_BYTES (ATTN_F*4)   // 47872 B

// ---------------------------------------------------------------------------
// Kernel 1: Q/K/V projections (proven)
// ---------------------------------------------------------------------------
__global__ __launch_bounds__(256) void qkv_kernel(
    const float* __restrict__ h,
    const float* __restrict__ Wq, const float* __restrict__ Wk, const float* __restrict__ Wv)
{
    extern __shared__ float sm_q[];
    float* sW = sm_q;
    float* sh = sm_q + 12288;
    const int t = threadIdx.x, c = t & 63, r = t >> 6;
    const int row0 = blockIdx.x * 8;
#pragma unroll
    for (int rep = 0; rep < 16; ++rep) sW[rep*256 + t]        = Wq[rep*256 + t];
#pragma unroll
    for (int rep = 0; rep < 16; ++rep) sW[4096 + rep*256 + t] = Wk[rep*256 + t];
#pragma unroll
    for (int rep = 0; rep < 16; ++rep) sW[8192 + rep*256 + t] = Wv[rep*256 + t];
    sh[t]       = h[row0*64 + t];
    sh[256 + t] = h[row0*64 + 256 + t];
    __syncthreads();

    const int rA = r, rB = r + 4;
    float q0=0,k0=0,v0=0,q1=0,k1=0,v1=0;
#pragma unroll 16
    for (int d = 0; d < 64; ++d){
        const float wq = sW[d*64 + c];
        const float wk = sW[4096 + d*64 + c];
        const float wv = sW[8192 + d*64 + c];
        const float xa = sh[rA*64 + d];
        const float xb = sh[rB*64 + d];
        q0 += xa*wq; k0 += xa*wk; v0 += xa*wv;
        q1 += xb*wq; k1 += xb*wk; v1 += xb*wv;
    }
    const float kscale = 0.35355339059327373f; // DH^-0.5
    g_Q[(row0+rA)*64 + c] = q0;
    g_K[(row0+rA)*64 + c] = k0 * kscale;
    g_V[(row0+rA)*64 + c] = v0;
    g_Q[(row0+rB)*64 + c] = q1;
    g_K[(row0+rB)*64 + c] = k1 * kscale;
    g_V[(row0+rB)*64 + c] = v1;
}

// ---------------------------------------------------------------------------
// Kernel 2: attention. One block per (i,b), 256 threads = 8 warps, 3 blk/SM.
// P = e @ (We*Q_i) via fp16 m16n8k16, 2-product split:
//   e = ehi + elo (fp16 limbs, exact to 2^-22); w rounded to single fp16.
// 64 mma/warp (was 96). B stored fp16x2 with (dp->si) permutation so each
// fragment is one conflict-free LDS.64. K via __ldg; V via cp.async overlap.
// ---------------------------------------------------------------------------
__global__ __launch_bounds__(256, 3) void attn_kernel(
    const float* __restrict__ e,
    const float* __restrict__ We,
    const float* __restrict__ kRW)
{
    extern __shared__ __align__(16) float S[];
    const int t = threadIdx.x;
    const int w = t >> 5, l = t & 31;
    const int qq = l >> 2, rr = l & 3;      // fragment row / col-in-quad
    const int i = blockIdx.x, b = blockIdx.y;
    const int bi = b*NN + i;

    if (t < 64) S[SQ_OFF + t] = g_Q[bi*64 + t];
    if (t < 128) S[SRW_OFF + t] = kRW[bi*128 + t];
    __syncthreads();

    // ---- stage e limbs: epair[j][kp][{hi,lo}], stride 72 (8 iters/thread) ----
    const float* eg = e + (size_t)bi * (NN*DD);
#pragma unroll
    for (int it = 0; it < 8; ++it){
        const int f = it*256 + t;
        const int j = f >> 4, q4 = f & 15;
        const float4 v = *reinterpret_cast<const float4*>(eg + j*64 + q4*4);
        uint32_t hiA, loA, hiB, loB;
        split_pair_f16(v.x, v.y, hiA, loA);
        split_pair_f16(v.z, v.w, hiB, loB);
        *reinterpret_cast<uint4*>(&S[EP_OFF + j*72 + q4*4]) = make_uint4(hiA, loA, hiB, loB);
    }
    // ---- stage B fp16: B[hk][si], stride 40; si permutes dp so the two
    //      k-pairs of one fragment (dp, dp+4) are adjacent -> LDS.64 frag ----
#pragma unroll
    for (int rep = 0; rep < 8; ++rep){
        const int idx = rep*256 + t;
        const int hk = idx & 63, dp = idx >> 6;   // dp in [0,32)
        const float sq = S[SQ_OFF + hk];
        const float w0 = We[(2*dp)*64 + hk] * sq;
        const float w1 = We[(2*dp+1)*64 + hk] * sq;
        const int si = (dp >> 3)*8 + (dp & 3)*2 + ((dp & 4) >> 2);
        *reinterpret_cast<uint32_t*>(&S[B_OFF + hk*40 + si]) = f16pack(w0, w1);
    }
    __syncthreads();

    // ---- GEMM: warp w owns m-tile w (rows 16w..16w+15); 8 n-tiles; 4 ks ----
    float acc[8][4];
#pragma unroll
    for (int n = 0; n < 8; ++n)
#pragma unroll
        for (int x = 0; x < 4; ++x) acc[n][x] = 0.f;

#pragma unroll
    for (int ks = 0; ks < 4; ++ks){
        // A fragments for this warp's m-tile (8 regs live)
        uint32_t Ah[4], Al[4];
        {
            const int row = 16*w + qq;
            const int base = EP_OFF + row*72 + (ks*8 + rr)*2;
            const uint2 a0 = *reinterpret_cast<const uint2*>(&S[base]);
            const uint2 a1 = *reinterpret_cast<const uint2*>(&S[base + 8*72]);
            const uint2 a2 = *reinterpret_cast<const uint2*>(&S[base + 8]);
            const uint2 a3 = *reinterpret_cast<const uint2*>(&S[base + 8*72 + 8]);
            Ah[0] = a0.x; Al[0] = a0.y;
            Ah[1] = a1.x; Al[1] = a1.y;
            Ah[2] = a2.x; Al[2] = a2.y;
            Ah[3] = a3.x; Al[3] = a3.y;
        }
        // stream B per n-tile: one LDS.64 per fragment, 2 mma per n-tile
#pragma unroll
        for (int nt = 0; nt < 8; ++nt){
            const uint2 bb = *reinterpret_cast<const uint2*>(
                &S[B_OFF + (nt*8 + qq)*40 + ks*8 + rr*2]);
            uint32_t Bf[2] = {bb.x, bb.y};
            mma_f16(acc[nt], Ah, Bf);
            mma_f16(acc[nt], Al, Bf);
        }
    }
    __syncthreads();   // all frag reads done; both regions free

    // ---- prefetch V into the freed e-region via cp.async (overlaps score) ----
    {
        const uint32_t sbase = smem_u32(S);
        const float* Vg = g_V + (size_t)b*NN*64;
#pragma unroll
        for (int it = 0; it < 8; ++it){
            const int f = it*256 + t;
            const int j = f >> 4, q4 = f & 15;
            CP_ASYNC16(sbase + (uint32_t)(V_OFF + j*68 + q4*4)*4u, Vg + j*64 + q4*4);
        }
        CP_COMMIT();
    }

    // ---- score phase: acc regs + K direct from L2, quad butterfly reduce ----
    const float* Kg = g_K + (size_t)b*NN*64;
#pragma unroll
    for (int rh = 0; rh < 2; ++rh){
        const int row = 16*w + qq + 8*rh;
        const float* Kr = Kg + row*64 + 2*rr;
        float sc8[8];
#pragma unroll
        for (int nt = 0; nt < 8; ++nt){
            const float2 k2 = __ldg(reinterpret_cast<const float2*>(Kr + 8*nt));
            float p = acc[nt][2*rh]*k2.x + acc[nt][2*rh+1]*k2.y;
            p += __shfl_xor_sync(0xffffffffu, p, 1);
            p += __shfl_xor_sync(0xffffffffu, p, 2);
            sc8[nt] = p;
        }
        const float rw = S[SRW_OFF + row];
#pragma unroll
        for (int x = 0; x < 2; ++x){
            const int nt = 2*rr + x;
            const float s = fminf(fmaxf(sc8[nt], -5.f), 5.f);
            S[SS_OFF + nt*132 + row] = __expf(s) * rw;
        }
    }
    CP_WAIT0();
    __syncthreads();

    // ---- attn = (sS @ V) / denom, V from smem; 4-way j-split over u ----
    {
        const int o = t & 63, u = t >> 6;       // u in [0,4)
        const int hR = o >> 3;
        const float* Sr = S + SS_OFF + hR*132 + u*32;
        float vsum = 0.f, dsum = 0.f;
#pragma unroll
        for (int jj = 0; jj < 32; ++jj){
            const float s = Sr[jj];
            vsum += s * S[V_OFF + (u*32 + jj)*68 + o];
            dsum += s;
        }
        S[RED_OFF + t]       = vsum;
        S[RED_OFF + 256 + t] = dsum;
    }
    __syncthreads();
    if (t < 64){
        float v = 0.f, d = 0.f;
#pragma unroll
        for (int u = 0; u < 4; ++u){
            v += S[RED_OFF + u*64 + t];
            d += S[RED_OFF + 256 + u*64 + t];
        }
        g_attn[bi*64 + t] = v / fmaxf(d, 1e-6f);
    }
}

// ---------------------------------------------------------------------------
// Kernel 3: O-proj + residual + LN1 + FFN + LN2 (proven)
// ---------------------------------------------------------------------------
__global__ __launch_bounds__(256) void tail_kernel(
    const float* __restrict__ h,
    const float* __restrict__ Wo, const float* __restrict__ bo,
    const float* __restrict__ g1, const float* __restrict__ b1g,
    const float* __restrict__ W1, const float* __restrict__ b1,
    const float* __restrict__ W2, const float* __restrict__ b2,
    const float* __restrict__ g2, const float* __restrict__ b2g,
    float* __restrict__ out)
{
    __shared__ float sa[4][65];
    __shared__ float sx[4][65];
    __shared__ float shd[4][130];
    const int t = threadIdx.x, r = t >> 6, c = t & 63;
    const int row = blockIdx.x * 4 + r;

    sa[r][c] = g_attn[row*64 + c];
    __syncthreads();
    float x = bo[c] + h[row*64 + c];
#pragma unroll 8
    for (int d = 0; d < 64; ++d) x += sa[r][d] * Wo[d*64 + c];

    sx[r][c] = x;
    __syncthreads();
    float m = 0.f;
#pragma unroll 8
    for (int d = 0; d < 64; ++d) m += sx[r][d];
    m *= (1.f/64.f);
    float v = 0.f;
#pragma unroll 8
    for (int d = 0; d < 64; ++d){ const float df = sx[r][d] - m; v += df*df; }
    v *= (1.f/64.f);
    const float h1 = (x - m) * rsqrtf(v + 1e-5f) * g1[c] + b1g[c];
    __syncthreads();
    sx[r][c] = h1;
    __syncthreads();

    float a0 = b1[c], a1 = b1[c + 64];
#pragma unroll 8
    for (int d = 0; d < 64; ++d){
        const float xv = sx[r][d];
        a0 += xv * W1[d*128 + c];
        a1 += xv * W1[d*128 + c + 64];
    }
    shd[r][c]      = fmaxf(a0, 0.f);
    shd[r][c + 64] = fmaxf(a1, 0.f);
    __syncthreads();
    float ff = b2[c];
#pragma unroll 8
    for (int u = 0; u < 128; ++u) ff += shd[r][u] * W2[u*64 + c];
    const float x2 = h1 + ff;

    __syncthreads();
    sa[r][c] = x2;
    __syncthreads();
    float m2 = 0.f;
#pragma unroll 8
    for (int d = 0; d < 64; ++d) m2 += sa[r][d];
    m2 *= (1.f/64.f);
    float v2 = 0.f;
#pragma unroll 8
    for (int d = 0; d < 64; ++d){ const float df = sa[r][d] - m2; v2 += df*df; }
    v2 *= (1.f/64.f);
    out[row*64 + c] = (x2 - m2) * rsqrtf(v2 + 1e-5f) * g2[c] + b2g[c];
}

// ---------------------------------------------------------------------------
extern "C" void kernel_launch(void* const* d_in, const int* in_sizes, int n_in,
                              void* d_out, int out_size)
{
    (void)in_sizes; (void)n_in; (void)out_size;
    const float* h   = (const float*)d_in[0];
    const float* e   = (const float*)d_in[2];
    const float* kRW = (const float*)d_in[3];
    const float* Wq  = (const float*)d_in[4];
    const float* Wk  = (const float*)d_in[5];
    const float* We  = (const float*)d_in[6];
    const float* Wv  = (const float*)d_in[7];
    const float* Wo  = (const float*)d_in[8];
    const float* bo  = (const float*)d_in[9];
    const float* g1  = (const float*)d_in[10];
    const float* b1g = (const float*)d_in[11];
    const float* W1  = (const float*)d_in[12];
    const float* b1  = (const float*)d_in[13];
    const float* W2  = (const float*)d_in[14];
    const float* b2  = (const float*)d_in[15];
    const float* g2  = (const float*)d_in[16];
    const float* b2g = (const float*)d_in[17];
    float* out = (float*)d_out;

    const int qkv_smem = 12800 * 4;
    cudaFuncSetAttribute((const void*)qkv_kernel,
                         cudaFuncAttributeMaxDynamicSharedMemorySize, qkv_smem);
    cudaFuncSetAttribute((const void*)attn_kernel,
                         cudaFuncAttributeMaxDynamicSharedMemorySize, ATTN_SMEM_BYTES);

    qkv_kernel<<<BB*NN/8, 256, qkv_smem>>>(h, Wq, Wk, Wv);
    dim3 grid(NN, BB);
    attn_kernel<<<grid, 256, ATTN_SMEM_BYTES>>>(e, We, kRW);
    tail_kernel<<<BB*NN/4, 256>>>(h, Wo, bo, g1, b1g, W1, b1, W2, b2, g2, b2g, out);
}

// round 16
// speedup vs baseline: 1.2276x; 1.0577x over previous
#include <cuda_runtime.h>
#include <cuda_fp16.h>
#include <cstdint>

#define BB 32
#define NN 128
#define DD 64
#define HH 8

// intermediates (device globals — no allocation allowed)
__device__ float g_Q[BB*NN*DD];
__device__ float g_K[BB*NN*DD];
__device__ float g_V[BB*NN*DD];
__device__ float g_attn[BB*NN*DD];

// ---------------------------------------------------------------------------
// helpers (portable PTX ISA, sm_80+, compiles for plain sm_103)
// ---------------------------------------------------------------------------
__device__ __forceinline__ void mma_f16(float* c, const uint32_t* a, const uint32_t* b){
    asm("mma.sync.aligned.m16n8k16.row.col.f32.f16.f16.f32 "
        "{%0,%1,%2,%3}, {%4,%5,%6,%7}, {%8,%9}, {%0,%1,%2,%3};"
        : "+f"(c[0]), "+f"(c[1]), "+f"(c[2]), "+f"(c[3])
        : "r"(a[0]), "r"(a[1]), "r"(a[2]), "r"(a[3]), "r"(b[0]), "r"(b[1]));
}
__device__ __forceinline__ uint32_t f16pack(float x, float y){
    const __half2 hh = __float22half2_rn(make_float2(x, y));
    return *reinterpret_cast<const uint32_t*>(&hh);
}
__device__ __forceinline__ uint32_t smem_u32(const void* p){
    uint32_t a;
    asm("{ .reg .u64 t; cvta.to.shared.u64 t, %1; cvt.u32.u64 %0, t; }" : "=r"(a) : "l"(p));
    return a;
}
#define CP_ASYNC16(dst, src) \
    asm volatile("cp.async.ca.shared.global [%0], [%1], 16;" :: "r"(dst), "l"(src))
#define CP_COMMIT() asm volatile("cp.async.commit_group;" ::: "memory")
#define CP_WAIT0()  asm volatile("cp.async.wait_group 0;" ::: "memory")

// smem layout (float offsets).
// Region1 (9216 f): e fp16 [128][36] (4608 f) -> V tile [128][68] + red @8704
// Region2 (2560 f): B fp16 [64][40] -> scores [8][132]
#define EP_OFF 0
#define V_OFF  0
#define RED_OFF 8704
#define B_OFF  9216
#define SS_OFF 9216
#define SQ_OFF 11776
#define SRW_OFF 11840
#define ATTN_F 11968
#define ATTN_SMEM_BYTES (ATTN_F*4)   // 47872 B

// ---------------------------------------------------------------------------
// Kernel 1: Q/K/V projections (proven)
// ---------------------------------------------------------------------------
__global__ __launch_bounds__(256) void qkv_kernel(
    const float* __restrict__ h,
    const float* __restrict__ Wq, const float* __restrict__ Wk, const float* __restrict__ Wv)
{
    extern __shared__ float sm_q[];
    float* sW = sm_q;
    float* sh = sm_q + 12288;
    const int t = threadIdx.x, c = t & 63, r = t >> 6;
    const int row0 = blockIdx.x * 8;
#pragma unroll
    for (int rep = 0; rep < 16; ++rep) sW[rep*256 + t]        = Wq[rep*256 + t];
#pragma unroll
    for (int rep = 0; rep < 16; ++rep) sW[4096 + rep*256 + t] = Wk[rep*256 + t];
#pragma unroll
    for (int rep = 0; rep < 16; ++rep) sW[8192 + rep*256 + t] = Wv[rep*256 + t];
    sh[t]       = h[row0*64 + t];
    sh[256 + t] = h[row0*64 + 256 + t];
    __syncthreads();

    const int rA = r, rB = r + 4;
    float q0=0,k0=0,v0=0,q1=0,k1=0,v1=0;
#pragma unroll 16
    for (int d = 0; d < 64; ++d){
        const float wq = sW[d*64 + c];
        const float wk = sW[4096 + d*64 + c];
        const float wv = sW[8192 + d*64 + c];
        const float xa = sh[rA*64 + d];
        const float xb = sh[rB*64 + d];
        q0 += xa*wq; k0 += xa*wk; v0 += xa*wv;
        q1 += xb*wq; k1 += xb*wk; v1 += xb*wv;
    }
    const float kscale = 0.35355339059327373f; // DH^-0.5
    g_Q[(row0+rA)*64 + c] = q0;
    g_K[(row0+rA)*64 + c] = k0 * kscale;
    g_V[(row0+rA)*64 + c] = v0;
    g_Q[(row0+rB)*64 + c] = q1;
    g_K[(row0+rB)*64 + c] = k1 * kscale;
    g_V[(row0+rB)*64 + c] = v1;
}

// ---------------------------------------------------------------------------
// Kernel 2: attention. One block per (i,b), 256 threads = 8 warps, 3 blk/SM.
// P = e @ (We*Q_i) via fp16 m16n8k16, SINGLE product (e and w both fp16-rn;
// measured pipeline sensitivity to GEMM rounding: ~2e-7 per operand).
// 32 mma/warp. e stored fp16x2 [j][kp] stride 36 (conflict-free LDS.32 frags);
// B stored fp16x2 with (dp->si) permutation -> one LDS.64 per fragment.
// K via __ldg; V via cp.async overlapped with the score phase.
// ---------------------------------------------------------------------------
__global__ __launch_bounds__(256, 3) void attn_kernel(
    const float* __restrict__ e,
    const float* __restrict__ We,
    const float* __restrict__ kRW)
{
    extern __shared__ __align__(16) float S[];
    const int t = threadIdx.x;
    const int w = t >> 5, l = t & 31;
    const int qq = l >> 2, rr = l & 3;      // fragment row / col-in-quad
    const int i = blockIdx.x, b = blockIdx.y;
    const int bi = b*NN + i;

    if (t < 64) S[SQ_OFF + t] = g_Q[bi*64 + t];
    if (t < 128) S[SRW_OFF + t] = kRW[bi*128 + t];
    __syncthreads();

    // ---- stage e fp16: [j][kp] stride 36, 8 iters/thread, STS.64 ----
    const float* eg = e + (size_t)bi * (NN*DD);
#pragma unroll
    for (int it = 0; it < 8; ++it){
        const int f = it*256 + t;
        const int j = f >> 4, q4 = f & 15;
        const float4 v = *reinterpret_cast<const float4*>(eg + j*64 + q4*4);
        const uint32_t p0 = f16pack(v.x, v.y);
        const uint32_t p1 = f16pack(v.z, v.w);
        *reinterpret_cast<uint2*>(&S[EP_OFF + j*36 + 2*q4]) = make_uint2(p0, p1);
    }
    // ---- stage B fp16: B[hk][si], stride 40; si permutes dp so the two
    //      k-pairs of one fragment (dp, dp+4) are adjacent -> LDS.64 frag ----
#pragma unroll
    for (int rep = 0; rep < 8; ++rep){
        const int idx = rep*256 + t;
        const int hk = idx & 63, dp = idx >> 6;   // dp in [0,32)
        const float sq = S[SQ_OFF + hk];
        const float w0 = We[(2*dp)*64 + hk] * sq;
        const float w1 = We[(2*dp+1)*64 + hk] * sq;
        const int si = (dp >> 3)*8 + (dp & 3)*2 + ((dp & 4) >> 2);
        *reinterpret_cast<uint32_t*>(&S[B_OFF + hk*40 + si]) = f16pack(w0, w1);
    }
    __syncthreads();

    // ---- GEMM: warp w owns m-tile w (rows 16w..16w+15); 8 n-tiles; 4 ks ----
    float acc[8][4];
#pragma unroll
    for (int n = 0; n < 8; ++n)
#pragma unroll
        for (int x = 0; x < 4; ++x) acc[n][x] = 0.f;

#pragma unroll
    for (int ks = 0; ks < 4; ++ks){
        // A fragment: 4 conflict-free LDS.32
        uint32_t Af[4];
        {
            const int row = 16*w + qq;
            const int base = EP_OFF + row*36 + ks*8 + rr;
            Af[0] = *reinterpret_cast<const uint32_t*>(&S[base]);
            Af[1] = *reinterpret_cast<const uint32_t*>(&S[base + 8*36]);
            Af[2] = *reinterpret_cast<const uint32_t*>(&S[base + 4]);
            Af[3] = *reinterpret_cast<const uint32_t*>(&S[base + 8*36 + 4]);
        }
        // stream B per n-tile: one LDS.64 per fragment, 1 mma per n-tile
#pragma unroll
        for (int nt = 0; nt < 8; ++nt){
            const uint2 bb = *reinterpret_cast<const uint2*>(
                &S[B_OFF + (nt*8 + qq)*40 + ks*8 + rr*2]);
            uint32_t Bf[2] = {bb.x, bb.y};
            mma_f16(acc[nt], Af, Bf);
        }
    }
    __syncthreads();   // all frag reads done; both regions free

    // ---- prefetch V into the freed e-region via cp.async (overlaps score) ----
    {
        const uint32_t sbase = smem_u32(S);
        const float* Vg = g_V + (size_t)b*NN*64;
#pragma unroll
        for (int it = 0; it < 8; ++it){
            const int f = it*256 + t;
            const int j = f >> 4, q4 = f & 15;
            CP_ASYNC16(sbase + (uint32_t)(V_OFF + j*68 + q4*4)*4u, Vg + j*64 + q4*4);
        }
        CP_COMMIT();
    }

    // ---- score phase: acc regs + K direct from L2, quad butterfly reduce ----
    const float* Kg = g_K + (size_t)b*NN*64;
#pragma unroll
    for (int rh = 0; rh < 2; ++rh){
        const int row = 16*w + qq + 8*rh;
        const float* Kr = Kg + row*64 + 2*rr;
        float sc8[8];
#pragma unroll
        for (int nt = 0; nt < 8; ++nt){
            const float2 k2 = __ldg(reinterpret_cast<const float2*>(Kr + 8*nt));
            float p = acc[nt][2*rh]*k2.x + acc[nt][2*rh+1]*k2.y;
            p += __shfl_xor_sync(0xffffffffu, p, 1);
            p += __shfl_xor_sync(0xffffffffu, p, 2);
            sc8[nt] = p;
        }
        const float rw = S[SRW_OFF + row];
#pragma unroll
        for (int x = 0; x < 2; ++x){
            const int nt = 2*rr + x;
            const float s = fminf(fmaxf(sc8[nt], -5.f), 5.f);
            S[SS_OFF + nt*132 + row] = __expf(s) * rw;
        }
    }
    CP_WAIT0();
    __syncthreads();

    // ---- attn = (sS @ V) / denom, V from smem; 4-way j-split over u ----
    {
        const int o = t & 63, u = t >> 6;       // u in [0,4)
        const int hR = o >> 3;
        const float* Sr = S + SS_OFF + hR*132 + u*32;
        float vsum = 0.f, dsum = 0.f;
#pragma unroll
        for (int jj = 0; jj < 32; ++jj){
            const float s = Sr[jj];
            vsum += s * S[V_OFF + (u*32 + jj)*68 + o];
            dsum += s;
        }
        S[RED_OFF + t]       = vsum;
        S[RED_OFF + 256 + t] = dsum;
    }
    __syncthreads();
    if (t < 64){
        float v = 0.f, d = 0.f;
#pragma unroll
        for (int u = 0; u < 4; ++u){
            v += S[RED_OFF + u*64 + t];
            d += S[RED_OFF + 256 + u*64 + t];
        }
        g_attn[bi*64 + t] = v / fmaxf(d, 1e-6f);
    }
}

// ---------------------------------------------------------------------------
// Kernel 3: O-proj + residual + LN1 + FFN + LN2 (proven)
// ---------------------------------------------------------------------------
__global__ __launch_bounds__(256) void tail_kernel(
    const float* __restrict__ h,
    const float* __restrict__ Wo, const float* __restrict__ bo,
    const float* __restrict__ g1, const float* __restrict__ b1g,
    const float* __restrict__ W1, const float* __restrict__ b1,
    const float* __restrict__ W2, const float* __restrict__ b2,
    const float* __restrict__ g2, const float* __restrict__ b2g,
    float* __restrict__ out)
{
    __shared__ float sa[4][65];
    __shared__ float sx[4][65];
    __shared__ float shd[4][130];
    const int t = threadIdx.x, r = t >> 6, c = t & 63;
    const int row = blockIdx.x * 4 + r;

    sa[r][c] = g_attn[row*64 + c];
    __syncthreads();
    float x = bo[c] + h[row*64 + c];
#pragma unroll 8
    for (int d = 0; d < 64; ++d) x += sa[r][d] * Wo[d*64 + c];

    sx[r][c] = x;
    __syncthreads();
    float m = 0.f;
#pragma unroll 8
    for (int d = 0; d < 64; ++d) m += sx[r][d];
    m *= (1.f/64.f);
    float v = 0.f;
#pragma unroll 8
    for (int d = 0; d < 64; ++d){ const float df = sx[r][d] - m; v += df*df; }
    v *= (1.f/64.f);
    const float h1 = (x - m) * rsqrtf(v + 1e-5f) * g1[c] + b1g[c];
    __syncthreads();
    sx[r][c] = h1;
    __syncthreads();

    float a0 = b1[c], a1 = b1[c + 64];
#pragma unroll 8
    for (int d = 0; d < 64; ++d){
        const float xv = sx[r][d];
        a0 += xv * W1[d*128 + c];
        a1 += xv * W1[d*128 + c + 64];
    }
    shd[r][c]      = fmaxf(a0, 0.f);
    shd[r][c + 64] = fmaxf(a1, 0.f);
    __syncthreads();
    float ff = b2[c];
#pragma unroll 8
    for (int u = 0; u < 128; ++u) ff += shd[r][u] * W2[u*64 + c];
    const float x2 = h1 + ff;

    __syncthreads();
    sa[r][c] = x2;
    __syncthreads();
    float m2 = 0.f;
#pragma unroll 8
    for (int d = 0; d < 64; ++d) m2 += sa[r][d];
    m2 *= (1.f/64.f);
    float v2 = 0.f;
#pragma unroll 8
    for (int d = 0; d < 64; ++d){ const float df = sa[r][d] - m2; v2 += df*df; }
    v2 *= (1.f/64.f);
    out[row*64 + c] = (x2 - m2) * rsqrtf(v2 + 1e-5f) * g2[c] + b2g[c];
}

// ---------------------------------------------------------------------------
extern "C" void kernel_launch(void* const* d_in, const int* in_sizes, int n_in,
                              void* d_out, int out_size)
{
    (void)in_sizes; (void)n_in; (void)out_size;
    const float* h   = (const float*)d_in[0];
    const float* e   = (const float*)d_in[2];
    const float* kRW = (const float*)d_in[3];
    const float* Wq  = (const float*)d_in[4];
    const float* Wk  = (const float*)d_in[5];
    const float* We  = (const float*)d_in[6];
    const float* Wv  = (const float*)d_in[7];
    const float* Wo  = (const float*)d_in[8];
    const float* bo  = (const float*)d_in[9];
    const float* g1  = (const float*)d_in[10];
    const float* b1g = (const float*)d_in[11];
    const float* W1  = (const float*)d_in[12];
    const float* b1  = (const float*)d_in[13];
    const float* W2  = (const float*)d_in[14];
    const float* b2  = (const float*)d_in[15];
    const float* g2  = (const float*)d_in[16];
    const float* b2g = (const float*)d_in[17];
    float* out = (float*)d_out;

    const int qkv_smem = 12800 * 4;
    cudaFuncSetAttribute((const void*)qkv_kernel,
                         cudaFuncAttributeMaxDynamicSharedMemorySize, qkv_smem);
    cudaFuncSetAttribute((const void*)attn_kernel,
                         cudaFuncAttributeMaxDynamicSharedMemorySize, ATTN_SMEM_BYTES);

    qkv_kernel<<<BB*NN/8, 256, qkv_smem>>>(h, Wq, Wk, Wv);
    dim3 grid(NN, BB);
    attn_kernel<<<grid, 256, ATTN_SMEM_BYTES>>>(e, We, kRW);
    tail_kernel<<<BB*NN/4, 256>>>(h, Wo, bo, g1, b1g, W1, b1, W2, b2, g2, b2g, out);
}

// round 17
// speedup vs baseline: 1.2437x; 1.0131x over previous
#include <cuda_runtime.h>
#include <cuda_fp16.h>
#include <cstdint>

#define BB 32
#define NN 128
#define DD 64
#define HH 8

// intermediates (device globals — no allocation allowed)
__device__ float g_Q[BB*NN*DD];
__device__ float g_K[BB*NN*DD];
__device__ float g_V[BB*NN*DD];
__device__ float g_attn[BB*NN*DD];

// ---------------------------------------------------------------------------
// helpers (portable PTX ISA, sm_80+, compiles for plain sm_103)
// ---------------------------------------------------------------------------
__device__ __forceinline__ void mma_f16(float* c, const uint32_t* a, const uint32_t* b){
    asm("mma.sync.aligned.m16n8k16.row.col.f32.f16.f16.f32 "
        "{%0,%1,%2,%3}, {%4,%5,%6,%7}, {%8,%9}, {%0,%1,%2,%3};"
        : "+f"(c[0]), "+f"(c[1]), "+f"(c[2]), "+f"(c[3])
        : "r"(a[0]), "r"(a[1]), "r"(a[2]), "r"(a[3]), "r"(b[0]), "r"(b[1]));
}
__device__ __forceinline__ uint32_t f16pack(float x, float y){
    const __half2 hh = __float22half2_rn(make_float2(x, y));
    return *reinterpret_cast<const uint32_t*>(&hh);
}
__device__ __forceinline__ uint32_t smem_u32(const void* p){
    uint32_t a;
    asm("{ .reg .u64 t; cvta.to.shared.u64 t, %1; cvt.u32.u64 %0, t; }" : "=r"(a) : "l"(p));
    return a;
}
#define CP_ASYNC16(dst, src) \
    asm volatile("cp.async.ca.shared.global [%0], [%1], 16;" :: "r"(dst), "l"(src))
#define CP_COMMIT() asm volatile("cp.async.commit_group;" ::: "memory")
#define CP_WAIT0()  asm volatile("cp.async.wait_group 0;" ::: "memory")

// attn smem layout (float offsets).
// Region1 (9216 f): e fp16 [128][36] (4608 f) -> V tile [128][68] + red @8704
// Region2 (2560 f): B fp16 [64][40] -> scores [8][132]
#define EP_OFF 0
#define V_OFF  0
#define RED_OFF 8704
#define B_OFF  9216
#define SS_OFF 9216
#define SQ_OFF 11776
#define SRW_OFF 11840
#define ATTN_F 11968
#define ATTN_SMEM_BYTES (ATTN_F*4)   // 47872 B

// ---------------------------------------------------------------------------
// Kernel 1: Q/K/V projections. 8 rows/block; weights staged via float4
// (12 LDG.128/thread instead of 48 scalar LDG).
// ---------------------------------------------------------------------------
__global__ __launch_bounds__(256) void qkv_kernel(
    const float* __restrict__ h,
    const float* __restrict__ Wq, const float* __restrict__ Wk, const float* __restrict__ Wv)
{
    extern __shared__ float sm_q[];
    float* sW = sm_q;            // 12288 f
    float* sh = sm_q + 12288;    // 512 f
    const int t = threadIdx.x, c = t & 63, r = t >> 6;
    const int row0 = blockIdx.x * 8;

    float4* sW4 = reinterpret_cast<float4*>(sW);
    const float4* Wq4 = reinterpret_cast<const float4*>(Wq);
    const float4* Wk4 = reinterpret_cast<const float4*>(Wk);
    const float4* Wv4 = reinterpret_cast<const float4*>(Wv);
#pragma unroll
    for (int rep = 0; rep < 4; ++rep) sW4[rep*256 + t]        = Wq4[rep*256 + t];
#pragma unroll
    for (int rep = 0; rep < 4; ++rep) sW4[1024 + rep*256 + t] = Wk4[rep*256 + t];
#pragma unroll
    for (int rep = 0; rep < 4; ++rep) sW4[2048 + rep*256 + t] = Wv4[rep*256 + t];
    if (t < 128)
        reinterpret_cast<float4*>(sh)[t] =
            reinterpret_cast<const float4*>(h + row0*64)[t];
    __syncthreads();

    const int rA = r, rB = r + 4;
    float q0=0,k0=0,v0=0,q1=0,k1=0,v1=0;
#pragma unroll 16
    for (int d = 0; d < 64; ++d){
        const float wq = sW[d*64 + c];
        const float wk = sW[4096 + d*64 + c];
        const float wv = sW[8192 + d*64 + c];
        const float xa = sh[rA*64 + d];
        const float xb = sh[rB*64 + d];
        q0 += xa*wq; k0 += xa*wk; v0 += xa*wv;
        q1 += xb*wq; k1 += xb*wk; v1 += xb*wv;
    }
    const float kscale = 0.35355339059327373f; // DH^-0.5
    g_Q[(row0+rA)*64 + c] = q0;
    g_K[(row0+rA)*64 + c] = k0 * kscale;
    g_V[(row0+rA)*64 + c] = v0;
    g_Q[(row0+rB)*64 + c] = q1;
    g_K[(row0+rB)*64 + c] = k1 * kscale;
    g_V[(row0+rB)*64 + c] = v1;
}

// ---------------------------------------------------------------------------
// Kernel 2: attention (byte-identical to the 108.7us R16 version).
// ---------------------------------------------------------------------------
__global__ __launch_bounds__(256, 3) void attn_kernel(
    const float* __restrict__ e,
    const float* __restrict__ We,
    const float* __restrict__ kRW)
{
    extern __shared__ __align__(16) float S[];
    const int t = threadIdx.x;
    const int w = t >> 5, l = t & 31;
    const int qq = l >> 2, rr = l & 3;      // fragment row / col-in-quad
    const int i = blockIdx.x, b = blockIdx.y;
    const int bi = b*NN + i;

    if (t < 64) S[SQ_OFF + t] = g_Q[bi*64 + t];
    if (t < 128) S[SRW_OFF + t] = kRW[bi*128 + t];
    __syncthreads();

    // ---- stage e fp16: [j][kp] stride 36, 8 iters/thread, STS.64 ----
    const float* eg = e + (size_t)bi * (NN*DD);
#pragma unroll
    for (int it = 0; it < 8; ++it){
        const int f = it*256 + t;
        const int j = f >> 4, q4 = f & 15;
        const float4 v = *reinterpret_cast<const float4*>(eg + j*64 + q4*4);
        const uint32_t p0 = f16pack(v.x, v.y);
        const uint32_t p1 = f16pack(v.z, v.w);
        *reinterpret_cast<uint2*>(&S[EP_OFF + j*36 + 2*q4]) = make_uint2(p0, p1);
    }
    // ---- stage B fp16: B[hk][si], stride 40; (dp->si) permutation ----
#pragma unroll
    for (int rep = 0; rep < 8; ++rep){
        const int idx = rep*256 + t;
        const int hk = idx & 63, dp = idx >> 6;   // dp in [0,32)
        const float sq = S[SQ_OFF + hk];
        const float w0 = We[(2*dp)*64 + hk] * sq;
        const float w1 = We[(2*dp+1)*64 + hk] * sq;
        const int si = (dp >> 3)*8 + (dp & 3)*2 + ((dp & 4) >> 2);
        *reinterpret_cast<uint32_t*>(&S[B_OFF + hk*40 + si]) = f16pack(w0, w1);
    }
    __syncthreads();

    // ---- GEMM: warp w owns m-tile w; 8 n-tiles; 4 ks; 1 mma each ----
    float acc[8][4];
#pragma unroll
    for (int n = 0; n < 8; ++n)
#pragma unroll
        for (int x = 0; x < 4; ++x) acc[n][x] = 0.f;

#pragma unroll
    for (int ks = 0; ks < 4; ++ks){
        uint32_t Af[4];
        {
            const int row = 16*w + qq;
            const int base = EP_OFF + row*36 + ks*8 + rr;
            Af[0] = *reinterpret_cast<const uint32_t*>(&S[base]);
            Af[1] = *reinterpret_cast<const uint32_t*>(&S[base + 8*36]);
            Af[2] = *reinterpret_cast<const uint32_t*>(&S[base + 4]);
            Af[3] = *reinterpret_cast<const uint32_t*>(&S[base + 8*36 + 4]);
        }
#pragma unroll
        for (int nt = 0; nt < 8; ++nt){
            const uint2 bb = *reinterpret_cast<const uint2*>(
                &S[B_OFF + (nt*8 + qq)*40 + ks*8 + rr*2]);
            uint32_t Bf[2] = {bb.x, bb.y};
            mma_f16(acc[nt], Af, Bf);
        }
    }
    __syncthreads();   // all frag reads done; both regions free

    // ---- prefetch V into the freed e-region via cp.async (overlaps score) ----
    {
        const uint32_t sbase = smem_u32(S);
        const float* Vg = g_V + (size_t)b*NN*64;
#pragma unroll
        for (int it = 0; it < 8; ++it){
            const int f = it*256 + t;
            const int j = f >> 4, q4 = f & 15;
            CP_ASYNC16(sbase + (uint32_t)(V_OFF + j*68 + q4*4)*4u, Vg + j*64 + q4*4);
        }
        CP_COMMIT();
    }

    // ---- score phase: acc regs + K direct from L2, quad butterfly reduce ----
    const float* Kg = g_K + (size_t)b*NN*64;
#pragma unroll
    for (int rh = 0; rh < 2; ++rh){
        const int row = 16*w + qq + 8*rh;
        const float* Kr = Kg + row*64 + 2*rr;
        float sc8[8];
#pragma unroll
        for (int nt = 0; nt < 8; ++nt){
            const float2 k2 = __ldg(reinterpret_cast<const float2*>(Kr + 8*nt));
            float p = acc[nt][2*rh]*k2.x + acc[nt][2*rh+1]*k2.y;
            p += __shfl_xor_sync(0xffffffffu, p, 1);
            p += __shfl_xor_sync(0xffffffffu, p, 2);
            sc8[nt] = p;
        }
        const float rw = S[SRW_OFF + row];
#pragma unroll
        for (int x = 0; x < 2; ++x){
            const int nt = 2*rr + x;
            const float s = fminf(fmaxf(sc8[nt], -5.f), 5.f);
            S[SS_OFF + nt*132 + row] = __expf(s) * rw;
        }
    }
    CP_WAIT0();
    __syncthreads();

    // ---- attn = (sS @ V) / denom, V from smem; 4-way j-split over u ----
    {
        const int o = t & 63, u = t >> 6;       // u in [0,4)
        const int hR = o >> 3;
        const float* Sr = S + SS_OFF + hR*132 + u*32;
        float vsum = 0.f, dsum = 0.f;
#pragma unroll
        for (int jj = 0; jj < 32; ++jj){
            const float s = Sr[jj];
            vsum += s * S[V_OFF + (u*32 + jj)*68 + o];
            dsum += s;
        }
        S[RED_OFF + t]       = vsum;
        S[RED_OFF + 256 + t] = dsum;
    }
    __syncthreads();
    if (t < 64){
        float v = 0.f, d = 0.f;
#pragma unroll
        for (int u = 0; u < 4; ++u){
            v += S[RED_OFF + u*64 + t];
            d += S[RED_OFF + 256 + u*64 + t];
        }
        g_attn[bi*64 + t] = v / fmaxf(d, 1e-6f);
    }
}

// ---------------------------------------------------------------------------
// Kernel 3: O-proj + residual + LN1 + FFN + LN2.
// 8 rows/block (512 blocks); all weights staged once per block via float4;
// each thread computes 2 rows so every staged weight feeds 2 FMAs.
// smem: Wo 4096 | W1 8192 | W2 8192 | sa 520 | sx 520 | shd 1040 = 22560 f.
// ---------------------------------------------------------------------------
__global__ __launch_bounds__(256) void tail_kernel(
    const float* __restrict__ h,
    const float* __restrict__ Wo, const float* __restrict__ bo,
    const float* __restrict__ g1, const float* __restrict__ b1g,
    const float* __restrict__ W1, const float* __restrict__ b1,
    const float* __restrict__ W2, const float* __restrict__ b2,
    const float* __restrict__ g2, const float* __restrict__ b2g,
    float* __restrict__ out)
{
    extern __shared__ float sm_t[];
    float* sW0 = sm_t;            // 4096
    float* sW1 = sm_t + 4096;     // 8192
    float* sW2 = sm_t + 12288;    // 8192
    float* sa  = sm_t + 20480;    // [8][65]
    float* sx  = sm_t + 21000;    // [8][65]
    float* shd = sm_t + 21520;    // [8][130]
    const int t = threadIdx.x, r = t >> 6, c = t & 63;
    const int row0 = blockIdx.x * 8;
    const int rA = r, rB = r + 4;

    // stage weights via float4: 4 + 8 + 8 = 20 LDG.128/thread
    {
        float4* d0 = reinterpret_cast<float4*>(sW0);
        const float4* s0 = reinterpret_cast<const float4*>(Wo);
#pragma unroll
        for (int rep = 0; rep < 4; ++rep) d0[rep*256 + t] = s0[rep*256 + t];
        float4* d1 = reinterpret_cast<float4*>(sW1);
        const float4* s1 = reinterpret_cast<const float4*>(W1);
#pragma unroll
        for (int rep = 0; rep < 8; ++rep) d1[rep*256 + t] = s1[rep*256 + t];
        float4* d2 = reinterpret_cast<float4*>(sW2);
        const float4* s2 = reinterpret_cast<const float4*>(W2);
#pragma unroll
        for (int rep = 0; rep < 8; ++rep) d2[rep*256 + t] = s2[rep*256 + t];
    }
    sa[rA*65 + c] = g_attn[(row0+rA)*64 + c];
    sa[rB*65 + c] = g_attn[(row0+rB)*64 + c];
    __syncthreads();

    // O projection + residual (2 rows/thread)
    float xA = bo[c] + h[(row0+rA)*64 + c];
    float xB = bo[c] + h[(row0+rB)*64 + c];
#pragma unroll 16
    for (int d = 0; d < 64; ++d){
        const float wv = sW0[d*64 + c];
        xA += sa[rA*65 + d] * wv;
        xB += sa[rB*65 + d] * wv;
    }

    // LN1
    sx[rA*65 + c] = xA;
    sx[rB*65 + c] = xB;
    __syncthreads();
    float h1A, h1B;
    {
        float mA = 0.f, mB = 0.f;
#pragma unroll 16
        for (int d = 0; d < 64; ++d){ mA += sx[rA*65 + d]; mB += sx[rB*65 + d]; }
        mA *= (1.f/64.f); mB *= (1.f/64.f);
        float vA = 0.f, vB = 0.f;
#pragma unroll 16
        for (int d = 0; d < 64; ++d){
            const float dA = sx[rA*65 + d] - mA; vA += dA*dA;
            const float dB = sx[rB*65 + d] - mB; vB += dB*dB;
        }
        vA *= (1.f/64.f); vB *= (1.f/64.f);
        h1A = (xA - mA) * rsqrtf(vA + 1e-5f) * g1[c] + b1g[c];
        h1B = (xB - mB) * rsqrtf(vB + 1e-5f) * g1[c] + b1g[c];
    }
    __syncthreads();
    sx[rA*65 + c] = h1A;
    sx[rB*65 + c] = h1B;
    __syncthreads();

    // FFN up (128 hidden; thread c owns units c and c+64, 2 rows)
    float a0A = b1[c], a1A = b1[c + 64];
    float a0B = a0A, a1B = a1A;
#pragma unroll 16
    for (int d = 0; d < 64; ++d){
        const float wa = sW1[d*128 + c];
        const float wb = sW1[d*128 + c + 64];
        const float xvA = sx[rA*65 + d];
        const float xvB = sx[rB*65 + d];
        a0A += xvA * wa; a1A += xvA * wb;
        a0B += xvB * wa; a1B += xvB * wb;
    }
    shd[rA*130 + c]      = fmaxf(a0A, 0.f);
    shd[rA*130 + c + 64] = fmaxf(a1A, 0.f);
    shd[rB*130 + c]      = fmaxf(a0B, 0.f);
    shd[rB*130 + c + 64] = fmaxf(a1B, 0.f);
    __syncthreads();
    float ffA = b2[c], ffB = ffA;
#pragma unroll 16
    for (int u = 0; u < 128; ++u){
        const float wv = sW2[u*64 + c];
        ffA += shd[rA*130 + u] * wv;
        ffB += shd[rB*130 + u] * wv;
    }
    const float x2A = h1A + ffA;
    const float x2B = h1B + ffB;

    // LN2
    __syncthreads();
    sa[rA*65 + c] = x2A;
    sa[rB*65 + c] = x2B;
    __syncthreads();
    {
        float mA = 0.f, mB = 0.f;
#pragma unroll 16
        for (int d = 0; d < 64; ++d){ mA += sa[rA*65 + d]; mB += sa[rB*65 + d]; }
        mA *= (1.f/64.f); mB *= (1.f/64.f);
        float vA = 0.f, vB = 0.f;
#pragma unroll 16
        for (int d = 0; d < 64; ++d){
            const float dA = sa[rA*65 + d] - mA; vA += dA*dA;
            const float dB = sa[rB*65 + d] - mB; vB += dB*dB;
        }
        vA *= (1.f/64.f); vB *= (1.f/64.f);
        out[(row0+rA)*64 + c] = (x2A - mA) * rsqrtf(vA + 1e-5f) * g2[c] + b2g[c];
        out[(row0+rB)*64 + c] = (x2B - mB) * rsqrtf(vB + 1e-5f) * g2[c] + b2g[c];
    }
}

// ---------------------------------------------------------------------------
extern "C" void kernel_launch(void* const* d_in, const int* in_sizes, int n_in,
                              void* d_out, int out_size)
{
    (void)in_sizes; (void)n_in; (void)out_size;
    const float* h   = (const float*)d_in[0];
    const float* e   = (const float*)d_in[2];
    const float* kRW = (const float*)d_in[3];
    const float* Wq  = (const float*)d_in[4];
    const float* Wk  = (const float*)d_in[5];
    const float* We  = (const float*)d_in[6];
    const float* Wv  = (const float*)d_in[7];
    const float* Wo  = (const float*)d_in[8];
    const float* bo  = (const float*)d_in[9];
    const float* g1  = (const float*)d_in[10];
    const float* b1g = (const float*)d_in[11];
    const float* W1  = (const float*)d_in[12];
    const float* b1  = (const float*)d_in[13];
    const float* W2  = (const float*)d_in[14];
    const float* b2  = (const float*)d_in[15];
    const float* g2  = (const float*)d_in[16];
    const float* b2g = (const float*)d_in[17];
    float* out = (float*)d_out;

    const int qkv_smem  = 12800 * 4;
    const int tail_smem = 22560 * 4;
    cudaFuncSetAttribute((const void*)qkv_kernel,
                         cudaFuncAttributeMaxDynamicSharedMemorySize, qkv_smem);
    cudaFuncSetAttribute((const void*)attn_kernel,
                         cudaFuncAttributeMaxDynamicSharedMemorySize, ATTN_SMEM_BYTES);
    cudaFuncSetAttribute((const void*)tail_kernel,
                         cudaFuncAttributeMaxDynamicSharedMemorySize, tail_smem);

    qkv_kernel<<<BB*NN/8, 256, qkv_smem>>>(h, Wq, Wk, Wv);
    dim3 grid(NN, BB);
    attn_kernel<<<grid, 256, ATTN_SMEM_BYTES>>>(e, We, kRW);
    tail_kernel<<<BB*NN/8, 256, tail_smem>>>(h, Wo, bo, g1, b1g, W1, b1, W2, b2, g2, b2g, out);
}